// round 14
// baseline (speedup 1.0000x reference)
#include <cuda_runtime.h>
#include <cuda_fp16.h>
#include <math.h>
#include <stdint.h>

#define NPIX (128*32*16*16)   // 1048576
#define VV 4096

struct Pair { float v; int i; };

// ---------------- static device scratch ----------------
__device__ float g_frest[NPIX];
__device__ float g_rsmall[128*32*169];
__device__ float g_eafrag[32*4224];     // 32 chunks x (1024 A-frag uint4 + 32 esq f4)
__device__ float g_bicW[9*16*4];
__device__ int   g_bicI[9*16*4];
__device__ Pair  g_part[32768*32];
__device__ int   g_idx[32768];
__device__ float g_loss;
__device__ unsigned int g_convdone;

// ---------------- helpers ----------------
__device__ __forceinline__ void mma_f16(float c[4], const uint32_t* a, uint32_t b0, uint32_t b1)
{
    asm volatile("mma.sync.aligned.m16n8k16.row.col.f32.f16.f16.f32 "
        "{%0,%1,%2,%3},{%4,%5,%6,%7},{%8,%9},{%0,%1,%2,%3};"
        : "+f"(c[0]), "+f"(c[1]), "+f"(c[2]), "+f"(c[3])
        : "r"(a[0]), "r"(a[1]), "r"(a[2]), "r"(a[3]), "r"(b0), "r"(b1));
}
__device__ __forceinline__ void ffma2(unsigned long long &d, unsigned long long a,
                                      unsigned long long b)
{
    asm("fma.rn.f32x2 %0, %1, %2, %0;" : "+l"(d) : "l"(a), "l"(b));
}
__device__ __forceinline__ unsigned long long dup2(float a)
{
    unsigned long long r;
    asm("mov.b64 %0, {%1, %1};" : "=l"(r) : "f"(a));
    return r;
}
__device__ __forceinline__ unsigned long long pack2(float lo, float hi)
{
    unsigned long long r;
    asm("mov.b64 %0, {%1, %2};" : "=l"(r) : "f"(lo), "f"(hi));
    return r;
}
__device__ __forceinline__ void unpack2(unsigned long long p, float &lo, float &hi)
{
    asm("mov.b64 {%0, %1}, %2;" : "=f"(lo), "=f"(hi) : "l"(p));
}
#define PREF_L1(p) asm volatile("prefetch.global.L1 [%0];" :: "l"(p))

// A'' element, pre-scaled by -2: k<64 -> hi(-2x), k>=64 -> lo(-2x)
__device__ __forceinline__ __half a_elem2(const float* emb, int code, int k)
{
    float x = -2.0f * emb[code*32 + (k & 31)];
    __half h = __float2half_rn(x);
    if (k < 64) return h;
    return __float2half_rn(x - __half2float(h));
}

// ---------------- fused setup: init (0..4095) | prep (4096..4227) | taps (4228) -------
__global__ void setup_kernel(const float* __restrict__ f, const float* __restrict__ emb,
                             float* __restrict__ out, float* __restrict__ frest,
                             float* __restrict__ rsmall, float* __restrict__ eaf)
{
    int bx = blockIdx.x, t = threadIdx.x;

    if (bx < 4096) {
        __shared__ float red[256];
        float v = f[bx*256 + t];
        frest[bx*256 + t] = v;
        out[bx*256 + t] = 0.f;
        red[t] = v;
        __syncthreads();
        for (int off = 128; off; off >>= 1) {
            if (t < off) red[t] += red[t + off];
            __syncthreads();
        }
        if (t == 0) rsmall[bx] = red[0] / 256.0f;
        if (bx == 0 && t == 0) { g_loss = 0.f; g_convdone = 0u; }
        return;
    }

    if (bx < 4228) {
        int e = (bx - 4096)*256 + t;            // < 33792 = 32*1056
        if (e >= 32*1056) return;
        int chunk = e / 1056;
        int i = e - chunk*1056;
        uint4* dst = (uint4*)(eaf + (size_t)chunk*4224);
        if (i < 1024) {
            int lane = i & 31;
            int r1 = i >> 5;                    // (cg*2 + mt)*4 + ks4
            int ks4 = r1 & 3;
            int q = r1 >> 2;
            int mt = q & 1, cg = q >> 1;
            int g = lane >> 2, tt = lane & 3;
            int row0 = chunk*128 + cg*32 + mt*16 + g;
            int row1 = row0 + 8;
            int seg = ks4 >> 1;                 // 0 = hi, 1 = lo
            int kk = (ks4 & 1)*16 + 2*tt;
            int k0 = seg*64 + kk;
            int k1 = k0 + 8;
            __half2 a0 = __halves2half2(a_elem2(emb, row0, k0), a_elem2(emb, row0, k0 + 1));
            __half2 a1 = __halves2half2(a_elem2(emb, row1, k0), a_elem2(emb, row1, k0 + 1));
            __half2 a2 = __halves2half2(a_elem2(emb, row0, k1), a_elem2(emb, row0, k1 + 1));
            __half2 a3 = __halves2half2(a_elem2(emb, row1, k1), a_elem2(emb, row1, k1 + 1));
            uint4 v;
            v.x = *(uint32_t*)&a0; v.y = *(uint32_t*)&a1;
            v.z = *(uint32_t*)&a2; v.w = *(uint32_t*)&a3;
            dst[i] = v;
        } else {
            int ii = i - 1024;                  // 0..31: esq frag [cg*8 + g]
            int cg = ii >> 3, g = ii & 7;
            float4 v; float* vv = &v.x;
            #pragma unroll
            for (int mt = 0; mt < 2; mt++)
                #pragma unroll
                for (int r = 0; r < 2; r++) {
                    int code = chunk*128 + cg*32 + mt*16 + r*8 + g;
                    float s = 0.f;
                    #pragma unroll
                    for (int c = 0; c < 32; c++) { float ee = emb[code*32 + c]; s = fmaf(ee, ee, s); }
                    vv[mt*2 + r] = s;
                }
            ((float4*)dst)[1024 + ii] = v;
        }
        return;
    }

    // taps
    if (t >= 144) return;
    int si = t >> 4, o = t & 15;
    const int pns[10] = {1,2,3,4,5,6,8,10,13,16};
    int in_s = pns[si];
    double src = (o + 0.5) * (double)in_s / 16.0 - 0.5;
    double fl = floor(src);
    const double a = -0.75;
    for (int tt = 0; tt < 4; tt++) {
        double x = fabs(src - (fl + (double)(tt - 1)));
        double w;
        if (x <= 1.0)      w = (a + 2.0)*x*x*x - (a + 3.0)*x*x + 1.0;
        else if (x < 2.0)  w = a*x*x*x - 5.0*a*x*x + 8.0*a*x - 4.0*a;
        else               w = 0.0;
        int idx = (int)fl + (tt - 1);
        if (idx < 0) idx = 0;
        if (idx > in_s - 1) idx = in_s - 1;
        g_bicW[(si*16 + o)*4 + tt] = (float)w;
        g_bicI[(si*16 + o)*4 + tt] = idx;
    }
}

// ---------------- NN search: dedup'd fp16 split, A from L2 + L1 prefetch -------------
__global__ __launch_bounds__(256, 2) void nn_mma_kernel(
        const float* __restrict__ rest, const float* __restrict__ eaf,
        int pp, int cpb, int split)
{
    __shared__ __align__(16) float sm[2560];
    int tid = threadIdx.x;
    int lane = tid & 31, warp = tid >> 5;
    int g = lane >> 2, t = lane & 3;
    int cg = warp & 3, vg = warp >> 2;
    int n0 = blockIdx.x << 6;
    int by = blockIdx.y;
    int cb0 = by * cpb;
    int ch0 = cb0 >> 7;
    int nb = cpb >> 7;

    // build B frags (vector side) into smem: [ks4][ntg][lane] uint2
    #pragma unroll
    for (int it = 0; it < 4; it++) {
        int e = tid + it*256;
        int ln = e & 31, ntg = (e >> 5) & 7, ks = e >> 8;
        int gg = ln >> 2, tt = ln & 3;
        int col = ntg*8 + gg;
        int n = n0 + col; int b = n / pp, rem = n - b*pp;
        int seg = ks >> 1;
        int kb = (ks & 1)*16 + 2*tt;
        const float* vbase = rest + (size_t)b*32*pp + rem;
        float x0 = vbase[(kb    )*pp];
        float x1 = vbase[(kb + 1)*pp];
        float x2 = vbase[(kb + 8)*pp];
        float x3 = vbase[(kb + 9)*pp];
        __half h0 = __float2half_rn(x0), h1 = __float2half_rn(x1);
        __half h2 = __float2half_rn(x2), h3 = __float2half_rn(x3);
        if (seg == 1) {
            h0 = __float2half_rn(x0 - __half2float(h0));
            h1 = __float2half_rn(x1 - __half2float(h1));
            h2 = __float2half_rn(x2 - __half2float(h2));
            h3 = __float2half_rn(x3 - __half2float(h3));
        }
        __half2 p0 = __halves2half2(h0, h1);
        __half2 p1 = __halves2half2(h2, h3);
        uint2 v; v.x = *(uint32_t*)&p0; v.y = *(uint32_t*)&p1;
        ((uint2*)sm)[e] = v;
    }
    __syncthreads();

    const uint2* sV2 = (const uint2*)sm;
    uint2 Bh[8], Bl[8];
    #pragma unroll
    for (int ks2 = 0; ks2 < 2; ks2++)
        #pragma unroll
        for (int nt = 0; nt < 4; nt++) {
            Bh[ks2*4 + nt] = sV2[((    ks2)*8 + vg*4 + nt)*32 + lane];
            Bl[ks2*4 + nt] = sV2[((2 + ks2)*8 + vg*4 + nt)*32 + lane];
        }

    float best[8]; int bidx[8];
    #pragma unroll
    for (int i = 0; i < 8; i++) { best[i] = 3.4e38f; bidx[i] = 0; }

    // L1-prefetch chunk 0
    {
        const uint4* cb = (const uint4*)(eaf + (size_t)ch0*4224);
        #pragma unroll
        for (int k4 = 0; k4 < 4; k4++) {
            PREF_L1(&cb[((cg*2 + 0)*4 + k4)*32 + lane]);
            PREF_L1(&cb[((cg*2 + 1)*4 + k4)*32 + lane]);
        }
        PREF_L1(&((const float4*)cb)[1024 + cg*8 + g]);
    }

    for (int j = 0; j < nb; j++) {
        const uint4* cb = (const uint4*)(eaf + (size_t)(ch0 + j)*4224);
        if (j + 1 < nb) {
            const uint4* cbn = (const uint4*)(eaf + (size_t)(ch0 + j + 1)*4224);
            #pragma unroll
            for (int k4 = 0; k4 < 4; k4++) {
                PREF_L1(&cbn[((cg*2 + 0)*4 + k4)*32 + lane]);
                PREF_L1(&cbn[((cg*2 + 1)*4 + k4)*32 + lane]);
            }
            PREF_L1(&((const float4*)cbn)[1024 + cg*8 + g]);
        }

        float4 es4 = ((const float4*)cb)[1024 + cg*8 + g];
        const float* esp = &es4.x;

        float C[2][4][4];
        #pragma unroll
        for (int mt = 0; mt < 2; mt++)
            #pragma unroll
            for (int nt = 0; nt < 4; nt++) {
                C[mt][nt][0] = esp[mt*2];     C[mt][nt][1] = esp[mt*2];
                C[mt][nt][2] = esp[mt*2 + 1]; C[mt][nt][3] = esp[mt*2 + 1];
            }

        uint4 Ah0 = cb[((cg*2 + 0)*4 + 0)*32 + lane];
        uint4 Ah1 = cb[((cg*2 + 0)*4 + 1)*32 + lane];
        uint4 Ah2 = cb[((cg*2 + 1)*4 + 0)*32 + lane];
        uint4 Ah3 = cb[((cg*2 + 1)*4 + 1)*32 + lane];

        #pragma unroll
        for (int nt = 0; nt < 4; nt++) {
            mma_f16(C[0][nt], (const uint32_t*)&Ah0, Bh[nt].x, Bh[nt].y);
            mma_f16(C[1][nt], (const uint32_t*)&Ah2, Bh[nt].x, Bh[nt].y);
        }
        #pragma unroll
        for (int nt = 0; nt < 4; nt++) {
            mma_f16(C[0][nt], (const uint32_t*)&Ah1, Bh[4 + nt].x, Bh[4 + nt].y);
            mma_f16(C[1][nt], (const uint32_t*)&Ah3, Bh[4 + nt].x, Bh[4 + nt].y);
        }
        #pragma unroll
        for (int nt = 0; nt < 4; nt++) {
            mma_f16(C[0][nt], (const uint32_t*)&Ah0, Bl[nt].x, Bl[nt].y);
            mma_f16(C[1][nt], (const uint32_t*)&Ah2, Bl[nt].x, Bl[nt].y);
        }
        #pragma unroll
        for (int nt = 0; nt < 4; nt++) {
            mma_f16(C[0][nt], (const uint32_t*)&Ah1, Bl[4 + nt].x, Bl[4 + nt].y);
            mma_f16(C[1][nt], (const uint32_t*)&Ah3, Bl[4 + nt].x, Bl[4 + nt].y);
        }
        uint4 Al0 = cb[((cg*2 + 0)*4 + 2)*32 + lane];
        uint4 Al1 = cb[((cg*2 + 0)*4 + 3)*32 + lane];
        uint4 Al2 = cb[((cg*2 + 1)*4 + 2)*32 + lane];
        uint4 Al3 = cb[((cg*2 + 1)*4 + 3)*32 + lane];
        #pragma unroll
        for (int nt = 0; nt < 4; nt++) {
            mma_f16(C[0][nt], (const uint32_t*)&Al0, Bh[nt].x, Bh[nt].y);
            mma_f16(C[1][nt], (const uint32_t*)&Al2, Bh[nt].x, Bh[nt].y);
        }
        #pragma unroll
        for (int nt = 0; nt < 4; nt++) {
            mma_f16(C[0][nt], (const uint32_t*)&Al1, Bh[4 + nt].x, Bh[4 + nt].y);
            mma_f16(C[1][nt], (const uint32_t*)&Al3, Bh[4 + nt].x, Bh[4 + nt].y);
        }

        // tree-min epilogue: candidates (mt,r) codes +0,+8,+16,+24 (ascending); strict <
        int codeb = cb0 + j*128 + cg*32 + g;
        #pragma unroll
        for (int nt = 0; nt < 4; nt++)
            #pragma unroll
            for (int q = 0; q < 2; q++) {
                float s00 = C[0][nt][q],     s01 = C[0][nt][2 + q];
                float s10 = C[1][nt][q],     s11 = C[1][nt][2 + q];
                float mv0 = s00; int mc0 = codeb;
                if (s01 < mv0) { mv0 = s01; mc0 = codeb + 8; }
                float mv1 = s10; int mc1 = codeb + 16;
                if (s11 < mv1) { mv1 = s11; mc1 = codeb + 24; }
                if (mv1 < mv0) { mv0 = mv1; mc0 = mc1; }
                int sl = nt*2 + q;
                if (mv0 < best[sl]) { best[sl] = mv0; bidx[sl] = mc0; }
            }
    }
    __syncthreads();

    #pragma unroll
    for (int sl = 0; sl < 8; sl++) {
        #pragma unroll
        for (int off = 4; off <= 16; off <<= 1) {
            float ov = __shfl_xor_sync(0xffffffffu, best[sl], off);
            int   oi = __shfl_xor_sync(0xffffffffu, bidx[sl], off);
            if (ov < best[sl] || (ov == best[sl] && oi < bidx[sl])) {
                best[sl] = ov; bidx[sl] = oi;
            }
        }
    }
    if (g == 0) {
        #pragma unroll
        for (int nt = 0; nt < 4; nt++)
            #pragma unroll
            for (int q = 0; q < 2; q++) {
                int vloc = vg*32 + nt*8 + 2*t + q;
                sm[2048 + vloc*4 + cg] = best[nt*2 + q];
                ((int*)sm)[2304 + vloc*4 + cg] = bidx[nt*2 + q];
            }
    }
    __syncthreads();
    if (tid < 64) {
        float v = sm[2048 + tid*4]; int bi = ((int*)sm)[2304 + tid*4];
        #pragma unroll
        for (int c2 = 1; c2 < 4; c2++) {
            float ov = sm[2048 + tid*4 + c2];
            int   oi = ((int*)sm)[2304 + tid*4 + c2];
            if (ov < v || (ov == v && oi < bi)) { v = ov; bi = oi; }
        }
        if (split == 1) g_idx[n0 + tid] = bi;
        else            g_part[(size_t)(n0 + tid)*32 + by] = Pair{v, bi};
    }
}

// ---------------- fused conv: reduce + gather + bicubic + conv (vectorized) + pool ----
#define CONV_SMEM_B (21920*4)

__global__ __launch_bounds__(256, 2) void conv_update_kernel(
        float* __restrict__ outIdx, const float* __restrict__ emb,
        const float* __restrict__ W, const float* __restrict__ bias,
        const float* __restrict__ f,
        float* __restrict__ fhat, float* __restrict__ frest,
        float* __restrict__ rsmall,
        int pn, int si, int pnN, int doRest, int split, int finalize,
        float* __restrict__ out)
{
    extern __shared__ float smf[];
    float* sIn = smf;
    float* sW  = smf + 11520;
    float* sHs = smf + 16128;
    float* sTw = smf + 21536;
    int*   sTi = (int*)(smf + 21600);
    int*   sIdx = (int*)(smf + 21664);
    int bx = blockIdx.x, tid = threadIdx.x;
    int b = bx >> 1, half = bx & 1;
    int pp = pn * pn;

    for (int j = tid; j < 4608; j += 256) sW[j] = W[half*4608 + j];
    if (pn < 16 && tid < 64) { sTw[tid] = g_bicW[si*64 + tid]; sTi[tid] = g_bicI[si*64 + tid]; }
    if (tid < pp) {
        int n = b*pp + tid;
        int bi;
        if (split == 1) {
            bi = g_idx[n];
        } else {
            float v = 3.4e38f; bi = 0x7fffffff;
            for (int s = 0; s < split; s++) {
                Pair p = g_part[(size_t)n*32 + s];
                if (p.v < v || (p.v == v && p.i < bi)) { v = p.v; bi = p.i; }
            }
        }
        sIdx[tid] = bi;
        if (half == 0) outIdx[n] = (float)bi;
    }
    __syncthreads();

    if (pn < 16) {
        for (int j = tid; j < 32*pp; j += 256) {
            int c = j / pp, rem = j - c*pp;
            sHs[j] = emb[sIdx[rem]*32 + c];
        }
        __syncthreads();
    }

    for (int j = tid; j < 32*360; j += 256) {
        int x = j % 20; int t = j / 20; int y = t % 18; int c = t / 18;
        float v = 0.f;
        if (x >= 1 && x <= 16 && y >= 1 && y <= 16) {
            int oy = y - 1, ox = x - 1;
            if (pn == 16) {
                v = emb[sIdx[oy*16 + ox]*32 + c];
            } else {
                const float* Wy = sTw + oy*4; const int* Iy = sTi + oy*4;
                const float* Wx = sTw + ox*4; const int* Ix = sTi + ox*4;
                const float* base = sHs + c*pp;
                float acc = 0.f;
                #pragma unroll
                for (int txp = 0; txp < 4; txp++) {
                    float col = 0.f;
                    #pragma unroll
                    for (int typ = 0; typ < 4; typ++)
                        col = fmaf(Wy[typ], base[Iy[typ]*pn + Ix[txp]], col);
                    acc = fmaf(Wx[txp], col, acc);
                }
                v = acc;
            }
        }
        sIn[j] = v;
    }
    __syncthreads();

    int warp = tid >> 5, lane = tid & 31;
    int y = lane >> 1, x0 = (lane & 1)*8;

    unsigned long long acc2[2][4];
    #pragma unroll
    for (int q = 0; q < 2; q++)
        #pragma unroll
        for (int mi = 0; mi < 4; mi++) acc2[q][mi] = 0ull;

    for (int ci = 0; ci < 32; ci++) {
        const float* inC = sIn + ci*360;
        const float* wC  = sW + (warp*2)*288 + ci*9;
        #pragma unroll
        for (int dy = 0; dy < 3; dy++) {
            const float* r = inC + (y + dy)*20 + x0;
            float4 ra = *(const float4*)r;
            float4 rb = *(const float4*)(r + 4);
            float2 rc = *(const float2*)(r + 8);
            unsigned long long pe0 = pack2(ra.x, ra.y);
            unsigned long long pe1 = pack2(ra.z, ra.w);
            unsigned long long pe2 = pack2(rb.x, rb.y);
            unsigned long long pe3 = pack2(rb.z, rb.w);
            unsigned long long pe4 = pack2(rc.x, rc.y);
            unsigned long long po0 = pack2(ra.y, ra.z);
            unsigned long long po1 = pack2(ra.w, rb.x);
            unsigned long long po2 = pack2(rb.y, rb.z);
            unsigned long long po3 = pack2(rb.w, rc.x);
            {
                unsigned long long w0 = dup2(wC[dy*3 + 0]);
                unsigned long long w1 = dup2(wC[288 + dy*3 + 0]);
                ffma2(acc2[0][0], w0, pe0); ffma2(acc2[0][1], w0, pe1);
                ffma2(acc2[0][2], w0, pe2); ffma2(acc2[0][3], w0, pe3);
                ffma2(acc2[1][0], w1, pe0); ffma2(acc2[1][1], w1, pe1);
                ffma2(acc2[1][2], w1, pe2); ffma2(acc2[1][3], w1, pe3);
            }
            {
                unsigned long long w0 = dup2(wC[dy*3 + 1]);
                unsigned long long w1 = dup2(wC[288 + dy*3 + 1]);
                ffma2(acc2[0][0], w0, po0); ffma2(acc2[0][1], w0, po1);
                ffma2(acc2[0][2], w0, po2); ffma2(acc2[0][3], w0, po3);
                ffma2(acc2[1][0], w1, po0); ffma2(acc2[1][1], w1, po1);
                ffma2(acc2[1][2], w1, po2); ffma2(acc2[1][3], w1, po3);
            }
            {
                unsigned long long w0 = dup2(wC[dy*3 + 2]);
                unsigned long long w1 = dup2(wC[288 + dy*3 + 2]);
                ffma2(acc2[0][0], w0, pe1); ffma2(acc2[0][1], w0, pe2);
                ffma2(acc2[0][2], w0, pe3); ffma2(acc2[0][3], w0, pe4);
                ffma2(acc2[1][0], w1, pe1); ffma2(acc2[1][1], w1, pe2);
                ffma2(acc2[1][2], w1, pe3); ffma2(acc2[1][3], w1, pe4);
            }
        }
    }
    __syncthreads();

    float acc[2][8];
    #pragma unroll
    for (int q = 0; q < 2; q++)
        #pragma unroll
        for (int mi = 0; mi < 4; mi++)
            unpack2(acc2[q][mi], acc[q][2*mi], acc[q][2*mi + 1]);

    float* sFr = sW;
    float lsum = 0.f;
    #pragma unroll
    for (int q = 0; q < 2; q++) {
        int co_loc = warp*2 + q;
        int co = half*16 + co_loc;
        float bv = bias[co];
        #pragma unroll
        for (int m = 0; m < 8; m++) {
            int px = x0 + m;
            int gi = ((b*32 + co)*16 + y)*16 + px;
            float hv = sIn[co*360 + (y + 1)*20 + (px + 1)];
            float h = hv*0.5f + (acc[q][m] + bv)*0.5f;
            float fh = fhat[gi] + h;
            fhat[gi] = fh;
            if (doRest) {
                float fr = frest[gi] - h;
                frest[gi] = fr;
                sFr[co_loc*256 + y*16 + px] = fr;
            }
            float d = fh - f[gi];
            lsum += d*d;
        }
    }
    #pragma unroll
    for (int off = 16; off; off >>= 1) lsum += __shfl_down_sync(0xffffffffu, lsum, off);
    if (lane == 0) atomicAdd(&g_loss, lsum);

    if (pnN > 0) {
        __syncthreads();
        int ppN = pnN * pnN;
        for (int j = tid; j < 16*ppN; j += 256) {
            int ox = j % pnN; int t2 = j / pnN;
            int oy = t2 % pnN; int c_loc = t2 / pnN;
            int c = half*16 + c_loc;
            int sy0 = (oy*16)/pnN,      sy1 = ((oy+1)*16 + pnN - 1)/pnN;
            int sx0 = (ox*16)/pnN,      sx1 = ((ox+1)*16 + pnN - 1)/pnN;
            const float* base = sFr + c_loc*256;
            float s = 0.f;
            for (int yy = sy0; yy < sy1; yy++)
                for (int xx = sx0; xx < sx1; xx++)
                    s += base[yy*16 + xx];
            rsmall[((size_t)(b*32 + c))*ppN + oy*pnN + ox] = s / (float)((sy1-sy0)*(sx1-sx0));
        }
    }

    if (finalize) {
        __syncthreads();
        if (tid == 0) {
            __threadfence();
            unsigned int old = atomicAdd(&g_convdone, 1u);
            if (old == gridDim.x - 1u) {
                __threadfence();
                out[NPIX] = g_loss * 1.25f / 10.0f / 1048576.0f;
                g_convdone = 0u;
            }
        }
    }
}

// =====================================================================================
extern "C" void kernel_launch(void* const* d_in, const int* in_sizes, int n_in,
                              void* d_out, int out_size)
{
    const float* f    = (const float*)d_in[0];
    const float* emb  = (const float*)d_in[1];
    const float* phiW = (const float*)d_in[2];
    const float* phib = (const float*)d_in[3];
    float* out = (float*)d_out;

    float *frest, *rsmall, *eaf;
    cudaGetSymbolAddress((void**)&frest,  g_frest);
    cudaGetSymbolAddress((void**)&rsmall, g_rsmall);
    cudaGetSymbolAddress((void**)&eaf,    g_eafrag);

    static const int pns[10]    = {1,2,3,4,5,6,8,10,13,16};
    static const int splits[10] = {32,16,8,8,4,2,2,1,1,1};

    int kmap[10];
    {
        double start = 1.0/(3.0*4.0);
        double stop  = 1.0 - 1.0/(3.0*4.0);
        double step  = (stop - start)/3.0;
        double ticks[4];
        for (int i2 = 0; i2 < 4; i2++) ticks[i2] = (double)i2*step + start;
        ticks[3] = stop;
        for (int si = 0; si < 10; si++) {
            double s = (double)si / 9.0;
            int bk = 0; double bvv = fabs(ticks[0] - s);
            for (int i2 = 1; i2 < 4; i2++) {
                double vv = fabs(ticks[i2] - s);
                if (vv < bvv) { bvv = vv; bk = i2; }
            }
            kmap[si] = bk;
        }
    }

    cudaFuncSetAttribute(conv_update_kernel,
                         cudaFuncAttributeMaxDynamicSharedMemorySize, CONV_SMEM_B);

    setup_kernel<<<4229, 256>>>(f, emb, out, frest, rsmall, eaf);

    float* idxbase = out + NPIX + 1;
    int idxoff = 0;
    for (int si = 0; si < 10; si++) {
        int pn = pns[si], pp = pn*pn;
        int N = 128*pp;
        const float* rest = (si == 9) ? frest : rsmall;

        int split = splits[si];
        dim3 g(N/64, split);
        nn_mma_kernel<<<g, 256>>>(rest, eaf, pp, VV/split, split);

        int pnN      = (si <= 7) ? pns[si+1] : 0;
        int doRest   = (si <= 8) ? 1 : 0;
        int finalize = (si == 9) ? 1 : 0;
        conv_update_kernel<<<256, 256, CONV_SMEM_B>>>(idxbase + idxoff, emb,
                phiW + kmap[si]*32*32*9, phib + kmap[si]*32, f, out, frest, rsmall,
                pn, si, pnN, doRest, split, finalize, out);
        idxoff += N;
    }
}

// round 15
// speedup vs baseline: 1.0379x; 1.0379x over previous
#include <cuda_runtime.h>
#include <cuda_fp16.h>
#include <math.h>
#include <stdint.h>

#define NPIX (128*32*16*16)   // 1048576
#define VV 4096

struct Pair { float v; int i; };

// ---------------- static device scratch ----------------
__device__ float g_frest[NPIX];
__device__ float g_rsmall[128*32*169];
__device__ float g_eafrag[32*4224];     // 32 chunks x (1024 A-frag uint4 + 32 esq f4)
__device__ float g_bicW[9*16*4];
__device__ int   g_bicI[9*16*4];
__device__ Pair  g_part[32768*32];
__device__ int   g_idx[32768];
__device__ float g_loss;
__device__ unsigned int g_convdone;

// ---------------- helpers ----------------
__device__ __forceinline__ void mma_f16(float c[4], const uint32_t* a, uint32_t b0, uint32_t b1)
{
    asm volatile("mma.sync.aligned.m16n8k16.row.col.f32.f16.f16.f32 "
        "{%0,%1,%2,%3},{%4,%5,%6,%7},{%8,%9},{%0,%1,%2,%3};"
        : "+f"(c[0]), "+f"(c[1]), "+f"(c[2]), "+f"(c[3])
        : "r"(a[0]), "r"(a[1]), "r"(a[2]), "r"(a[3]), "r"(b0), "r"(b1));
}
__device__ __forceinline__ void ffma2(unsigned long long &d, unsigned long long a,
                                      unsigned long long b)
{
    asm("fma.rn.f32x2 %0, %1, %2, %0;" : "+l"(d) : "l"(a), "l"(b));
}
__device__ __forceinline__ unsigned long long dup2(float a)
{
    unsigned long long r;
    asm("mov.b64 %0, {%1, %1};" : "=l"(r) : "f"(a));
    return r;
}
__device__ __forceinline__ unsigned long long pack2(float lo, float hi)
{
    unsigned long long r;
    asm("mov.b64 %0, {%1, %2};" : "=l"(r) : "f"(lo), "f"(hi));
    return r;
}
__device__ __forceinline__ void unpack2(unsigned long long p, float &lo, float &hi)
{
    asm("mov.b64 {%0, %1}, %2;" : "=f"(lo), "=f"(hi) : "l"(p));
}

// A'' element, pre-scaled by -2: k<64 -> hi(-2x), k>=64 -> lo(-2x)
__device__ __forceinline__ __half a_elem2(const float* emb, int code, int k)
{
    float x = -2.0f * emb[code*32 + (k & 31)];
    __half h = __float2half_rn(x);
    if (k < 64) return h;
    return __float2half_rn(x - __half2float(h));
}

// ---------------- fused setup: init (0..4095) | prep (4096..4227) | taps (4228) -------
__global__ void setup_kernel(const float* __restrict__ f, const float* __restrict__ emb,
                             float* __restrict__ out, float* __restrict__ frest,
                             float* __restrict__ rsmall, float* __restrict__ eaf)
{
    int bx = blockIdx.x, t = threadIdx.x;

    if (bx < 4096) {
        __shared__ float red[256];
        float v = f[bx*256 + t];
        frest[bx*256 + t] = v;
        out[bx*256 + t] = 0.f;
        red[t] = v;
        __syncthreads();
        for (int off = 128; off; off >>= 1) {
            if (t < off) red[t] += red[t + off];
            __syncthreads();
        }
        if (t == 0) rsmall[bx] = red[0] / 256.0f;
        if (bx == 0 && t == 0) { g_loss = 0.f; g_convdone = 0u; }
        return;
    }

    if (bx < 4228) {
        int e = (bx - 4096)*256 + t;            // < 33792 = 32*1056
        if (e >= 32*1056) return;
        int chunk = e / 1056;
        int i = e - chunk*1056;
        uint4* dst = (uint4*)(eaf + (size_t)chunk*4224);
        if (i < 1024) {
            int lane = i & 31;
            int r1 = i >> 5;                    // (cg*2 + mt)*4 + ks4
            int ks4 = r1 & 3;
            int q = r1 >> 2;
            int mt = q & 1, cg = q >> 1;
            int g = lane >> 2, tt = lane & 3;
            int row0 = chunk*128 + cg*32 + mt*16 + g;
            int row1 = row0 + 8;
            int seg = ks4 >> 1;                 // 0 = hi, 1 = lo
            int kk = (ks4 & 1)*16 + 2*tt;
            int k0 = seg*64 + kk;
            int k1 = k0 + 8;
            __half2 a0 = __halves2half2(a_elem2(emb, row0, k0), a_elem2(emb, row0, k0 + 1));
            __half2 a1 = __halves2half2(a_elem2(emb, row1, k0), a_elem2(emb, row1, k0 + 1));
            __half2 a2 = __halves2half2(a_elem2(emb, row0, k1), a_elem2(emb, row0, k1 + 1));
            __half2 a3 = __halves2half2(a_elem2(emb, row1, k1), a_elem2(emb, row1, k1 + 1));
            uint4 v;
            v.x = *(uint32_t*)&a0; v.y = *(uint32_t*)&a1;
            v.z = *(uint32_t*)&a2; v.w = *(uint32_t*)&a3;
            dst[i] = v;
        } else {
            int ii = i - 1024;                  // 0..31: esq frag [cg*8 + g]
            int cg = ii >> 3, g = ii & 7;
            float4 v; float* vv = &v.x;
            #pragma unroll
            for (int mt = 0; mt < 2; mt++)
                #pragma unroll
                for (int r = 0; r < 2; r++) {
                    int code = chunk*128 + cg*32 + mt*16 + r*8 + g;
                    float s = 0.f;
                    #pragma unroll
                    for (int c = 0; c < 32; c++) { float ee = emb[code*32 + c]; s = fmaf(ee, ee, s); }
                    vv[mt*2 + r] = s;
                }
            ((float4*)dst)[1024 + ii] = v;
        }
        return;
    }

    // taps
    if (t >= 144) return;
    int si = t >> 4, o = t & 15;
    const int pns[10] = {1,2,3,4,5,6,8,10,13,16};
    int in_s = pns[si];
    double src = (o + 0.5) * (double)in_s / 16.0 - 0.5;
    double fl = floor(src);
    const double a = -0.75;
    for (int tt = 0; tt < 4; tt++) {
        double x = fabs(src - (fl + (double)(tt - 1)));
        double w;
        if (x <= 1.0)      w = (a + 2.0)*x*x*x - (a + 3.0)*x*x + 1.0;
        else if (x < 2.0)  w = a*x*x*x - 5.0*a*x*x + 8.0*a*x - 4.0*a;
        else               w = 0.0;
        int idx = (int)fl + (tt - 1);
        if (idx < 0) idx = 0;
        if (idx > in_s - 1) idx = in_s - 1;
        g_bicW[(si*16 + o)*4 + tt] = (float)w;
        g_bicI[(si*16 + o)*4 + tt] = idx;
    }
}

// ---------------- NN search: dedup'd fp16 split, all A-loads hoisted -----------------
__global__ __launch_bounds__(256, 2) void nn_mma_kernel(
        const float* __restrict__ rest, const float* __restrict__ eaf,
        int pp, int cpb, int split)
{
    __shared__ __align__(16) float sm[2560];
    int tid = threadIdx.x;
    int lane = tid & 31, warp = tid >> 5;
    int g = lane >> 2, t = lane & 3;
    int cg = warp & 3, vg = warp >> 2;
    int n0 = blockIdx.x << 6;
    int by = blockIdx.y;
    int cb0 = by * cpb;
    int ch0 = cb0 >> 7;
    int nb = cpb >> 7;

    // build B frags (vector side) into smem: [ks4][ntg][lane] uint2
    #pragma unroll
    for (int it = 0; it < 4; it++) {
        int e = tid + it*256;
        int ln = e & 31, ntg = (e >> 5) & 7, ks = e >> 8;
        int gg = ln >> 2, tt = ln & 3;
        int col = ntg*8 + gg;
        int n = n0 + col; int b = n / pp, rem = n - b*pp;
        int seg = ks >> 1;
        int kb = (ks & 1)*16 + 2*tt;
        const float* vbase = rest + (size_t)b*32*pp + rem;
        float x0 = vbase[(kb    )*pp];
        float x1 = vbase[(kb + 1)*pp];
        float x2 = vbase[(kb + 8)*pp];
        float x3 = vbase[(kb + 9)*pp];
        __half h0 = __float2half_rn(x0), h1 = __float2half_rn(x1);
        __half h2 = __float2half_rn(x2), h3 = __float2half_rn(x3);
        if (seg == 1) {
            h0 = __float2half_rn(x0 - __half2float(h0));
            h1 = __float2half_rn(x1 - __half2float(h1));
            h2 = __float2half_rn(x2 - __half2float(h2));
            h3 = __float2half_rn(x3 - __half2float(h3));
        }
        __half2 p0 = __halves2half2(h0, h1);
        __half2 p1 = __halves2half2(h2, h3);
        uint2 v; v.x = *(uint32_t*)&p0; v.y = *(uint32_t*)&p1;
        ((uint2*)sm)[e] = v;
    }
    __syncthreads();

    const uint2* sV2 = (const uint2*)sm;
    uint2 Bh[8], Bl[8];
    #pragma unroll
    for (int ks2 = 0; ks2 < 2; ks2++)
        #pragma unroll
        for (int nt = 0; nt < 4; nt++) {
            Bh[ks2*4 + nt] = sV2[((    ks2)*8 + vg*4 + nt)*32 + lane];
            Bl[ks2*4 + nt] = sV2[((2 + ks2)*8 + vg*4 + nt)*32 + lane];
        }

    float best[8]; int bidx[8];
    #pragma unroll
    for (int i = 0; i < 8; i++) { best[i] = 3.4e38f; bidx[i] = 0; }

    for (int j = 0; j < nb; j++) {
        const uint4* cb = (const uint4*)(eaf + (size_t)(ch0 + j)*4224);

        // hoist ALL chunk loads up front (8 LDG.128 + 1 LDG.128 esq, independent)
        uint4 Ah0 = cb[((cg*2 + 0)*4 + 0)*32 + lane];
        uint4 Ah1 = cb[((cg*2 + 0)*4 + 1)*32 + lane];
        uint4 Ah2 = cb[((cg*2 + 1)*4 + 0)*32 + lane];
        uint4 Ah3 = cb[((cg*2 + 1)*4 + 1)*32 + lane];
        uint4 Al0 = cb[((cg*2 + 0)*4 + 2)*32 + lane];
        uint4 Al1 = cb[((cg*2 + 0)*4 + 3)*32 + lane];
        uint4 Al2 = cb[((cg*2 + 1)*4 + 2)*32 + lane];
        uint4 Al3 = cb[((cg*2 + 1)*4 + 3)*32 + lane];
        float4 es4 = ((const float4*)cb)[1024 + cg*8 + g];
        const float* esp = &es4.x;

        float C[2][4][4];
        #pragma unroll
        for (int mt = 0; mt < 2; mt++)
            #pragma unroll
            for (int nt = 0; nt < 4; nt++) {
                C[mt][nt][0] = esp[mt*2];     C[mt][nt][1] = esp[mt*2];
                C[mt][nt][2] = esp[mt*2 + 1]; C[mt][nt][3] = esp[mt*2 + 1];
            }

        #pragma unroll
        for (int nt = 0; nt < 4; nt++) {
            mma_f16(C[0][nt], (const uint32_t*)&Ah0, Bh[nt].x, Bh[nt].y);
            mma_f16(C[1][nt], (const uint32_t*)&Ah2, Bh[nt].x, Bh[nt].y);
        }
        #pragma unroll
        for (int nt = 0; nt < 4; nt++) {
            mma_f16(C[0][nt], (const uint32_t*)&Ah1, Bh[4 + nt].x, Bh[4 + nt].y);
            mma_f16(C[1][nt], (const uint32_t*)&Ah3, Bh[4 + nt].x, Bh[4 + nt].y);
        }
        #pragma unroll
        for (int nt = 0; nt < 4; nt++) {
            mma_f16(C[0][nt], (const uint32_t*)&Ah0, Bl[nt].x, Bl[nt].y);
            mma_f16(C[1][nt], (const uint32_t*)&Ah2, Bl[nt].x, Bl[nt].y);
        }
        #pragma unroll
        for (int nt = 0; nt < 4; nt++) {
            mma_f16(C[0][nt], (const uint32_t*)&Ah1, Bl[4 + nt].x, Bl[4 + nt].y);
            mma_f16(C[1][nt], (const uint32_t*)&Ah3, Bl[4 + nt].x, Bl[4 + nt].y);
        }
        #pragma unroll
        for (int nt = 0; nt < 4; nt++) {
            mma_f16(C[0][nt], (const uint32_t*)&Al0, Bh[nt].x, Bh[nt].y);
            mma_f16(C[1][nt], (const uint32_t*)&Al2, Bh[nt].x, Bh[nt].y);
        }
        #pragma unroll
        for (int nt = 0; nt < 4; nt++) {
            mma_f16(C[0][nt], (const uint32_t*)&Al1, Bh[4 + nt].x, Bh[4 + nt].y);
            mma_f16(C[1][nt], (const uint32_t*)&Al3, Bh[4 + nt].x, Bh[4 + nt].y);
        }

        // tree-min epilogue: candidates codes +0,+8,+16,+24 (ascending); strict <
        int codeb = cb0 + j*128 + cg*32 + g;
        #pragma unroll
        for (int nt = 0; nt < 4; nt++)
            #pragma unroll
            for (int q = 0; q < 2; q++) {
                float s00 = C[0][nt][q],     s01 = C[0][nt][2 + q];
                float s10 = C[1][nt][q],     s11 = C[1][nt][2 + q];
                float mv0 = s00; int mc0 = codeb;
                if (s01 < mv0) { mv0 = s01; mc0 = codeb + 8; }
                float mv1 = s10; int mc1 = codeb + 16;
                if (s11 < mv1) { mv1 = s11; mc1 = codeb + 24; }
                if (mv1 < mv0) { mv0 = mv1; mc0 = mc1; }
                int sl = nt*2 + q;
                if (mv0 < best[sl]) { best[sl] = mv0; bidx[sl] = mc0; }
            }
    }
    __syncthreads();

    #pragma unroll
    for (int sl = 0; sl < 8; sl++) {
        #pragma unroll
        for (int off = 4; off <= 16; off <<= 1) {
            float ov = __shfl_xor_sync(0xffffffffu, best[sl], off);
            int   oi = __shfl_xor_sync(0xffffffffu, bidx[sl], off);
            if (ov < best[sl] || (ov == best[sl] && oi < bidx[sl])) {
                best[sl] = ov; bidx[sl] = oi;
            }
        }
    }
    if (g == 0) {
        #pragma unroll
        for (int nt = 0; nt < 4; nt++)
            #pragma unroll
            for (int q = 0; q < 2; q++) {
                int vloc = vg*32 + nt*8 + 2*t + q;
                sm[2048 + vloc*4 + cg] = best[nt*2 + q];
                ((int*)sm)[2304 + vloc*4 + cg] = bidx[nt*2 + q];
            }
    }
    __syncthreads();
    if (tid < 64) {
        float v = sm[2048 + tid*4]; int bi = ((int*)sm)[2304 + tid*4];
        #pragma unroll
        for (int c2 = 1; c2 < 4; c2++) {
            float ov = sm[2048 + tid*4 + c2];
            int   oi = ((int*)sm)[2304 + tid*4 + c2];
            if (ov < v || (ov == v && oi < bi)) { v = ov; bi = oi; }
        }
        if (split == 1) g_idx[n0 + tid] = bi;
        else            g_part[(size_t)(n0 + tid)*32 + by] = Pair{v, bi};
    }
}

// ---------------- fused conv: reduce + gather + bicubic + conv (vectorized) + pool ----
#define CONV_SMEM_B (21920*4)

__global__ __launch_bounds__(256, 2) void conv_update_kernel(
        float* __restrict__ outIdx, const float* __restrict__ emb,
        const float* __restrict__ W, const float* __restrict__ bias,
        const float* __restrict__ f,
        float* __restrict__ fhat, float* __restrict__ frest,
        float* __restrict__ rsmall,
        int pn, int si, int pnN, int doRest, int split, int finalize,
        float* __restrict__ out)
{
    extern __shared__ float smf[];
    float* sIn = smf;
    float* sW  = smf + 11520;
    float* sHs = smf + 16128;
    float* sTw = smf + 21536;
    int*   sTi = (int*)(smf + 21600);
    int*   sIdx = (int*)(smf + 21664);
    int bx = blockIdx.x, tid = threadIdx.x;
    int b = bx >> 1, half = bx & 1;
    int pp = pn * pn;

    for (int j = tid; j < 4608; j += 256) sW[j] = W[half*4608 + j];
    if (pn < 16 && tid < 64) { sTw[tid] = g_bicW[si*64 + tid]; sTi[tid] = g_bicI[si*64 + tid]; }
    if (tid < pp) {
        int n = b*pp + tid;
        int bi;
        if (split == 1) {
            bi = g_idx[n];
        } else {
            float v = 3.4e38f; bi = 0x7fffffff;
            for (int s = 0; s < split; s++) {
                Pair p = g_part[(size_t)n*32 + s];
                if (p.v < v || (p.v == v && p.i < bi)) { v = p.v; bi = p.i; }
            }
        }
        sIdx[tid] = bi;
        if (half == 0) outIdx[n] = (float)bi;
    }
    __syncthreads();

    if (pn < 16) {
        for (int j = tid; j < 32*pp; j += 256) {
            int c = j / pp, rem = j - c*pp;
            sHs[j] = emb[sIdx[rem]*32 + c];
        }
        __syncthreads();
    }

    for (int j = tid; j < 32*360; j += 256) {
        int x = j % 20; int t = j / 20; int y = t % 18; int c = t / 18;
        float v = 0.f;
        if (x >= 1 && x <= 16 && y >= 1 && y <= 16) {
            int oy = y - 1, ox = x - 1;
            if (pn == 16) {
                v = emb[sIdx[oy*16 + ox]*32 + c];
            } else {
                const float* Wy = sTw + oy*4; const int* Iy = sTi + oy*4;
                const float* Wx = sTw + ox*4; const int* Ix = sTi + ox*4;
                const float* base = sHs + c*pp;
                float acc = 0.f;
                #pragma unroll
                for (int txp = 0; txp < 4; txp++) {
                    float col = 0.f;
                    #pragma unroll
                    for (int typ = 0; typ < 4; typ++)
                        col = fmaf(Wy[typ], base[Iy[typ]*pn + Ix[txp]], col);
                    acc = fmaf(Wx[txp], col, acc);
                }
                v = acc;
            }
        }
        sIn[j] = v;
    }
    __syncthreads();

    int warp = tid >> 5, lane = tid & 31;
    int y = lane >> 1, x0 = (lane & 1)*8;

    unsigned long long acc2[2][4];
    #pragma unroll
    for (int q = 0; q < 2; q++)
        #pragma unroll
        for (int mi = 0; mi < 4; mi++) acc2[q][mi] = 0ull;

    for (int ci = 0; ci < 32; ci++) {
        const float* inC = sIn + ci*360;
        const float* wC  = sW + (warp*2)*288 + ci*9;
        #pragma unroll
        for (int dy = 0; dy < 3; dy++) {
            const float* r = inC + (y + dy)*20 + x0;
            float4 ra = *(const float4*)r;
            float4 rb = *(const float4*)(r + 4);
            float2 rc = *(const float2*)(r + 8);
            unsigned long long pe0 = pack2(ra.x, ra.y);
            unsigned long long pe1 = pack2(ra.z, ra.w);
            unsigned long long pe2 = pack2(rb.x, rb.y);
            unsigned long long pe3 = pack2(rb.z, rb.w);
            unsigned long long pe4 = pack2(rc.x, rc.y);
            unsigned long long po0 = pack2(ra.y, ra.z);
            unsigned long long po1 = pack2(ra.w, rb.x);
            unsigned long long po2 = pack2(rb.y, rb.z);
            unsigned long long po3 = pack2(rb.w, rc.x);
            {
                unsigned long long w0 = dup2(wC[dy*3 + 0]);
                unsigned long long w1 = dup2(wC[288 + dy*3 + 0]);
                ffma2(acc2[0][0], w0, pe0); ffma2(acc2[0][1], w0, pe1);
                ffma2(acc2[0][2], w0, pe2); ffma2(acc2[0][3], w0, pe3);
                ffma2(acc2[1][0], w1, pe0); ffma2(acc2[1][1], w1, pe1);
                ffma2(acc2[1][2], w1, pe2); ffma2(acc2[1][3], w1, pe3);
            }
            {
                unsigned long long w0 = dup2(wC[dy*3 + 1]);
                unsigned long long w1 = dup2(wC[288 + dy*3 + 1]);
                ffma2(acc2[0][0], w0, po0); ffma2(acc2[0][1], w0, po1);
                ffma2(acc2[0][2], w0, po2); ffma2(acc2[0][3], w0, po3);
                ffma2(acc2[1][0], w1, po0); ffma2(acc2[1][1], w1, po1);
                ffma2(acc2[1][2], w1, po2); ffma2(acc2[1][3], w1, po3);
            }
            {
                unsigned long long w0 = dup2(wC[dy*3 + 2]);
                unsigned long long w1 = dup2(wC[288 + dy*3 + 2]);
                ffma2(acc2[0][0], w0, pe1); ffma2(acc2[0][1], w0, pe2);
                ffma2(acc2[0][2], w0, pe3); ffma2(acc2[0][3], w0, pe4);
                ffma2(acc2[1][0], w1, pe1); ffma2(acc2[1][1], w1, pe2);
                ffma2(acc2[1][2], w1, pe3); ffma2(acc2[1][3], w1, pe4);
            }
        }
    }
    __syncthreads();

    float acc[2][8];
    #pragma unroll
    for (int q = 0; q < 2; q++)
        #pragma unroll
        for (int mi = 0; mi < 4; mi++)
            unpack2(acc2[q][mi], acc[q][2*mi], acc[q][2*mi + 1]);

    float* sFr = sW;
    float lsum = 0.f;
    #pragma unroll
    for (int q = 0; q < 2; q++) {
        int co_loc = warp*2 + q;
        int co = half*16 + co_loc;
        float bv = bias[co];
        #pragma unroll
        for (int m = 0; m < 8; m++) {
            int px = x0 + m;
            int gi = ((b*32 + co)*16 + y)*16 + px;
            float hv = sIn[co*360 + (y + 1)*20 + (px + 1)];
            float h = hv*0.5f + (acc[q][m] + bv)*0.5f;
            float fh = fhat[gi] + h;
            fhat[gi] = fh;
            if (doRest) {
                float fr = frest[gi] - h;
                frest[gi] = fr;
                sFr[co_loc*256 + y*16 + px] = fr;
            }
            float d = fh - f[gi];
            lsum += d*d;
        }
    }
    #pragma unroll
    for (int off = 16; off; off >>= 1) lsum += __shfl_down_sync(0xffffffffu, lsum, off);
    if (lane == 0) atomicAdd(&g_loss, lsum);

    if (pnN > 0) {
        __syncthreads();
        int ppN = pnN * pnN;
        for (int j = tid; j < 16*ppN; j += 256) {
            int ox = j % pnN; int t2 = j / pnN;
            int oy = t2 % pnN; int c_loc = t2 / pnN;
            int c = half*16 + c_loc;
            int sy0 = (oy*16)/pnN,      sy1 = ((oy+1)*16 + pnN - 1)/pnN;
            int sx0 = (ox*16)/pnN,      sx1 = ((ox+1)*16 + pnN - 1)/pnN;
            const float* base = sFr + c_loc*256;
            float s = 0.f;
            for (int yy = sy0; yy < sy1; yy++)
                for (int xx = sx0; xx < sx1; xx++)
                    s += base[yy*16 + xx];
            rsmall[((size_t)(b*32 + c))*ppN + oy*pnN + ox] = s / (float)((sy1-sy0)*(sx1-sx0));
        }
    }

    if (finalize) {
        __syncthreads();
        if (tid == 0) {
            __threadfence();
            unsigned int old = atomicAdd(&g_convdone, 1u);
            if (old == gridDim.x - 1u) {
                __threadfence();
                out[NPIX] = g_loss * 1.25f / 10.0f / 1048576.0f;
                g_convdone = 0u;
            }
        }
    }
}

// =====================================================================================
extern "C" void kernel_launch(void* const* d_in, const int* in_sizes, int n_in,
                              void* d_out, int out_size)
{
    const float* f    = (const float*)d_in[0];
    const float* emb  = (const float*)d_in[1];
    const float* phiW = (const float*)d_in[2];
    const float* phib = (const float*)d_in[3];
    float* out = (float*)d_out;

    float *frest, *rsmall, *eaf;
    cudaGetSymbolAddress((void**)&frest,  g_frest);
    cudaGetSymbolAddress((void**)&rsmall, g_rsmall);
    cudaGetSymbolAddress((void**)&eaf,    g_eafrag);

    static const int pns[10]    = {1,2,3,4,5,6,8,10,13,16};
    static const int splits[10] = {32,16,8,8,4,2,2,4,4,1};

    int kmap[10];
    {
        double start = 1.0/(3.0*4.0);
        double stop  = 1.0 - 1.0/(3.0*4.0);
        double step  = (stop - start)/3.0;
        double ticks[4];
        for (int i2 = 0; i2 < 4; i2++) ticks[i2] = (double)i2*step + start;
        ticks[3] = stop;
        for (int si = 0; si < 10; si++) {
            double s = (double)si / 9.0;
            int bk = 0; double bvv = fabs(ticks[0] - s);
            for (int i2 = 1; i2 < 4; i2++) {
                double vv = fabs(ticks[i2] - s);
                if (vv < bvv) { bvv = vv; bk = i2; }
            }
            kmap[si] = bk;
        }
    }

    cudaFuncSetAttribute(conv_update_kernel,
                         cudaFuncAttributeMaxDynamicSharedMemorySize, CONV_SMEM_B);

    setup_kernel<<<4229, 256>>>(f, emb, out, frest, rsmall, eaf);

    float* idxbase = out + NPIX + 1;
    int idxoff = 0;
    for (int si = 0; si < 10; si++) {
        int pn = pns[si], pp = pn*pn;
        int N = 128*pp;
        const float* rest = (si == 9) ? frest : rsmall;

        int split = splits[si];
        dim3 g(N/64, split);
        nn_mma_kernel<<<g, 256>>>(rest, eaf, pp, VV/split, split);

        int pnN      = (si <= 7) ? pns[si+1] : 0;
        int doRest   = (si <= 8) ? 1 : 0;
        int finalize = (si == 9) ? 1 : 0;
        conv_update_kernel<<<256, 256, CONV_SMEM_B>>>(idxbase + idxoff, emb,
                phiW + kmap[si]*32*32*9, phib + kmap[si]*32, f, out, frest, rsmall,
                pn, si, pnN, doRest, split, finalize, out);
        idxoff += N;
    }
}